// round 14
// baseline (speedup 1.0000x reference)
#include <cuda_runtime.h>
#include <cuda_bf16.h>

// ---------------------------------------------------------------------------
// Single fused kernel, LPT (largest-first) self-scheduling.
// CTA r processes the r-th LARGEST segment (ties by ascending index). Since
// blocks dispatch in ascending blockIdx order, big segments run first and the
// drain tail is filled by the smallest jobs.
//
// Prologue (per CTA, L2-hot):
//   1. stage node_num[0..B) into smem (coalesced)
//   2. 128-bin histogram of counts (values in [32,96])
//   3. thread 0: walk bins high->low to find this rank's (value v, k)
//   4. block scan to locate the k-th index with count==v  -> segment s
//   5. block reduce sum(scnt[0..s))                       -> start offset
// Mainloop/epilogue identical to the proven 45.8us body (.cs float4 stream).
// ---------------------------------------------------------------------------
__global__ __launch_bounds__(256, 8)
void segmean_kernel(const float* __restrict__ x,
                    const int*   __restrict__ node_num,
                    const float* __restrict__ W,     // [4,256]
                    const float* __restrict__ bias,  // [4]
                    float*       __restrict__ out,   // [B,4]
                    int B)
{
    __shared__ int   scnt[4096];
    __shared__ int   hist[128];
    __shared__ int   sh_vk[2];     // [0]=value bucket, [1]=k within bucket
    __shared__ int   sh_s;         // selected segment index
    __shared__ int   wred[8];
    __shared__ float part[8][4];

    const int t    = threadIdx.x;
    const int warp = t >> 5;
    const int lane = t & 31;
    const int r    = blockIdx.x;

    // ---- 1. stage counts (coalesced) + zero histogram ----
    for (int i = t; i < B; i += 256) scnt[i] = node_num[i];
    if (t < 128) hist[t] = 0;
    __syncthreads();

    // ---- 2. histogram ----
    for (int i = t; i < B; i += 256) atomicAdd(&hist[scnt[i] & 127], 1);
    __syncthreads();

    // ---- 3. rank -> (v, k): r-th largest ----
    if (t == 0) {
        int run = 0;
        for (int v = 127; v >= 0; --v) {
            int h = hist[v];
            if (r < run + h) { sh_vk[0] = v; sh_vk[1] = r - run; break; }
            run += h;
        }
    }
    __syncthreads();
    const int v = sh_vk[0];
    const int k = sh_vk[1];

    // ---- 4. find k-th (ascending index) occurrence of value v ----
    // blocked ownership: thread t owns indices [t*IT, t*IT+IT)
    const int IT   = (B + 255) >> 8;
    const int base = t * IT;
    int m = 0;
    for (int i = 0; i < IT; ++i) {
        int idx = base + i;
        if (idx < B && scnt[idx] == v) ++m;
    }
    int inc = m;                        // warp inclusive scan
    #pragma unroll
    for (int off = 1; off < 32; off <<= 1) {
        int n = __shfl_up_sync(0xFFFFFFFFu, inc, off);
        if (lane >= off) inc += n;
    }
    if (lane == 31) wred[warp] = inc;
    __syncthreads();
    int wbase = 0;
    #pragma unroll
    for (int w = 0; w < 8; ++w)
        if (w < warp) wbase += wred[w];
    const int excl = wbase + inc - m;   // exclusive prefix of matches
    if (k >= excl && k < excl + m) {
        int need = k - excl;
        for (int i = 0; i < IT; ++i) {
            int idx = base + i;
            if (idx < B && scnt[idx] == v) {
                if (need == 0) { sh_s = idx; break; }
                --need;
            }
        }
    }
    __syncthreads();
    const int s   = sh_s;
    const int cnt = v;

    // ---- 5. start = sum scnt[0..s) ----
    int partial = 0;
    for (int i = t; i < s; i += 256) partial += scnt[i];
    #pragma unroll
    for (int off = 16; off > 0; off >>= 1)
        partial += __shfl_down_sync(0xFFFFFFFFu, partial, off);
    if (lane == 0) wred[warp] = partial;
    __syncthreads();
    if (t == 0) {
        int ssum = 0;
        #pragma unroll
        for (int w = 0; w < 8; ++w) ssum += wred[w];
        wred[0] = ssum;
    }
    __syncthreads();
    const int start = wred[0];

    // ---- streaming column sums (proven body) ----
    const float4* p = reinterpret_cast<const float4*>(x + (size_t)start * 256) + t;

    float4 sA = make_float4(0.f, 0.f, 0.f, 0.f);
    float4 sB = make_float4(0.f, 0.f, 0.f, 0.f);

    const int nIter = cnt >> 2;             // 4-row groups
    int i = 0;
    for (; i + 2 <= nIter; i += 2) {
        float4 a = __ldcs(p);
        float4 c = __ldcs(p + 256);
        sA.x += a.x; sA.y += a.y; sA.z += a.z; sA.w += a.w;
        sB.x += c.x; sB.y += c.y; sB.z += c.z; sB.w += c.w;
        p += 512;
    }
    if (nIter & 1) {
        float4 a = __ldcs(p);
        sA.x += a.x; sA.y += a.y; sA.z += a.z; sA.w += a.w;
        p += 256;
    }
    const int tailN = (cnt & 3) << 6;       // tail rows as flat float4s
    if (t < tailN) {
        float4 a = __ldcs(p);
        sB.x += a.x; sB.y += a.y; sB.z += a.z; sB.w += a.w;
    }

    float4 sv;
    sv.x = sA.x + sB.x;
    sv.y = sA.y + sB.y;
    sv.z = sA.z + sB.z;
    sv.w = sA.w + sB.w;

    // ---- dots with W, reduce, sigmoid ----
    const int c4 = (t & 63) << 2;
    const float4 w0 = *reinterpret_cast<const float4*>(W + c4);
    const float4 w1 = *reinterpret_cast<const float4*>(W + 256 + c4);
    const float4 w2 = *reinterpret_cast<const float4*>(W + 512 + c4);
    const float4 w3 = *reinterpret_cast<const float4*>(W + 768 + c4);

    float p0 = sv.x * w0.x + sv.y * w0.y + sv.z * w0.z + sv.w * w0.w;
    float p1 = sv.x * w1.x + sv.y * w1.y + sv.z * w1.z + sv.w * w1.w;
    float p2 = sv.x * w2.x + sv.y * w2.y + sv.z * w2.z + sv.w * w2.w;
    float p3 = sv.x * w3.x + sv.y * w3.y + sv.z * w3.z + sv.w * w3.w;

    #pragma unroll
    for (int off = 16; off > 0; off >>= 1) {
        p0 += __shfl_down_sync(0xFFFFFFFFu, p0, off);
        p1 += __shfl_down_sync(0xFFFFFFFFu, p1, off);
        p2 += __shfl_down_sync(0xFFFFFFFFu, p2, off);
        p3 += __shfl_down_sync(0xFFFFFFFFu, p3, off);
    }

    if (lane == 0) {
        part[warp][0] = p0;
        part[warp][1] = p1;
        part[warp][2] = p2;
        part[warp][3] = p3;
    }
    __syncthreads();

    if (t < 4) {
        float acc = 0.f;
        #pragma unroll
        for (int w = 0; w < 8; ++w) acc += part[w][t];
        acc = bias[t] + acc / (float)cnt;
        out[(size_t)s * 4 + t] = 1.0f / (1.0f + __expf(-acc));
    }
}

extern "C" void kernel_launch(void* const* d_in, const int* in_sizes, int n_in,
                              void* d_out, int out_size) {
    const float* x        = (const float*)d_in[0];
    const int*   node_num = (const int*)  d_in[1];
    const float* W        = (const float*)d_in[2];
    const float* bias     = (const float*)d_in[3];
    float*       out      = (float*)d_out;

    const int B = in_sizes[1];   // 4096 segments

    segmean_kernel<<<B, 256>>>(x, node_num, W, bias, out, B);
}

// round 16
// speedup vs baseline: 1.2681x; 1.2681x over previous
#include <cuda_runtime.h>
#include <cuda_bf16.h>

// Cross-part combine state (zero-initialized at module load; each use resets)
__device__ float4 g_part4[8192 * 4];   // per (segment, quarter) partial dots
__device__ int    g_done[8192];        // arrival counters, reset by last arriver

// ---------------------------------------------------------------------------
// Fused segment-mean + GEMM + sigmoid, quarter-segment granularity.
// Grid = 4*B. CTA c handles quarter q = c&3 of segment s = c>>2:
//   rows [q*cnt/4, (q+1)*cnt/4)  (8..24 rows each for cnt in [32,96]).
// Prologue: self-scan for the segment start (L2-hot, same as 45.8us kernel).
// Mainloop: proven .cs float4 stream, thread t owns columns 4*(t&63)..+3.
// Epilogue: block-reduce dot-partials -> 4 floats; store slot; last of the 4
//           part-CTAs combines in fixed order, sigmoid, writes out, resets.
// ---------------------------------------------------------------------------
__global__ __launch_bounds__(256, 8)
void segmean_kernel(const float* __restrict__ x,
                    const int*   __restrict__ node_num,
                    const float* __restrict__ W,     // [4,256]
                    const float* __restrict__ bias,  // [4]
                    float*       __restrict__ out,   // [B,4]
                    int B)
{
    const int c    = blockIdx.x;
    const int s    = c >> 2;
    const int q    = c & 3;
    const int t    = threadIdx.x;
    const int warp = t >> 5;
    const int lane = t & 31;

    // ---- self-scan: start = sum node_num[0..s) ----
    int partial = 0;
    for (int i = t; i < s; i += 256)
        partial += __ldg(&node_num[i]);

    #pragma unroll
    for (int off = 16; off > 0; off >>= 1)
        partial += __shfl_down_sync(0xFFFFFFFFu, partial, off);

    __shared__ int wsum[8];
    if (lane == 0) wsum[warp] = partial;
    __syncthreads();
    if (t == 0) {
        int ssum = 0;
        #pragma unroll
        for (int w = 0; w < 8; ++w) ssum += wsum[w];
        wsum[0] = ssum;
    }
    __syncthreads();
    const int start = wsum[0];
    const int cnt   = __ldg(&node_num[s]);

    // this quarter's row range
    const int r0 = (q * cnt) >> 2;
    const int r1 = ((q + 1) * cnt) >> 2;
    const int n  = r1 - r0;

    // ---- streaming column sums over n rows ----
    const float4* p = reinterpret_cast<const float4*>(x + (size_t)(start + r0) * 256) + t;

    float4 sA = make_float4(0.f, 0.f, 0.f, 0.f);
    float4 sB = make_float4(0.f, 0.f, 0.f, 0.f);

    const int nIter = n >> 2;               // 4-row groups
    int i = 0;
    for (; i + 2 <= nIter; i += 2) {
        float4 a = __ldcs(p);
        float4 d = __ldcs(p + 256);
        sA.x += a.x; sA.y += a.y; sA.z += a.z; sA.w += a.w;
        sB.x += d.x; sB.y += d.y; sB.z += d.z; sB.w += d.w;
        p += 512;
    }
    if (nIter & 1) {
        float4 a = __ldcs(p);
        sA.x += a.x; sA.y += a.y; sA.z += a.z; sA.w += a.w;
        p += 256;
    }
    const int tailN = (n & 3) << 6;         // tail rows as flat float4s
    if (t < tailN) {
        float4 a = __ldcs(p);
        sB.x += a.x; sB.y += a.y; sB.z += a.z; sB.w += a.w;
    }

    float4 sv;
    sv.x = sA.x + sB.x;
    sv.y = sA.y + sB.y;
    sv.z = sA.z + sB.z;
    sv.w = sA.w + sB.w;

    // ---- partial dots with W over this thread's 4 columns ----
    const int c4 = (t & 63) << 2;
    const float4 w0 = *reinterpret_cast<const float4*>(W + c4);
    const float4 w1 = *reinterpret_cast<const float4*>(W + 256 + c4);
    const float4 w2 = *reinterpret_cast<const float4*>(W + 512 + c4);
    const float4 w3 = *reinterpret_cast<const float4*>(W + 768 + c4);

    float p0 = sv.x * w0.x + sv.y * w0.y + sv.z * w0.z + sv.w * w0.w;
    float p1 = sv.x * w1.x + sv.y * w1.y + sv.z * w1.z + sv.w * w1.w;
    float p2 = sv.x * w2.x + sv.y * w2.y + sv.z * w2.z + sv.w * w2.w;
    float p3 = sv.x * w3.x + sv.y * w3.y + sv.z * w3.z + sv.w * w3.w;

    #pragma unroll
    for (int off = 16; off > 0; off >>= 1) {
        p0 += __shfl_down_sync(0xFFFFFFFFu, p0, off);
        p1 += __shfl_down_sync(0xFFFFFFFFu, p1, off);
        p2 += __shfl_down_sync(0xFFFFFFFFu, p2, off);
        p3 += __shfl_down_sync(0xFFFFFFFFu, p3, off);
    }

    __shared__ float part[8][4];
    if (lane == 0) {
        part[warp][0] = p0;
        part[warp][1] = p1;
        part[warp][2] = p2;
        part[warp][3] = p3;
    }
    __syncthreads();

    // ---- single-thread combine/publish (t == 0) ----
    if (t == 0) {
        float4 mine;
        mine.x = part[0][0] + part[1][0] + part[2][0] + part[3][0]
               + part[4][0] + part[5][0] + part[6][0] + part[7][0];
        mine.y = part[0][1] + part[1][1] + part[2][1] + part[3][1]
               + part[4][1] + part[5][1] + part[6][1] + part[7][1];
        mine.z = part[0][2] + part[1][2] + part[2][2] + part[3][2]
               + part[4][2] + part[5][2] + part[6][2] + part[7][2];
        mine.w = part[0][3] + part[1][3] + part[2][3] + part[3][3]
               + part[4][3] + part[5][3] + part[6][3] + part[7][3];

        g_part4[(s << 2) + q] = mine;
        __threadfence();
        int old = atomicAdd(&g_done[s], 1);
        if (old == 3) {
            // last arriver: deterministic fixed-order combine
            float4 a0 = g_part4[(s << 2) + 0];
            float4 a1 = g_part4[(s << 2) + 1];
            float4 a2 = g_part4[(s << 2) + 2];
            float4 a3 = g_part4[(s << 2) + 3];
            const float inv = 1.0f / (float)cnt;
            const float4 bi = *reinterpret_cast<const float4*>(bias);
            float4 o4;
            o4.x = 1.0f / (1.0f + __expf(-(bi.x + (a0.x + a1.x + a2.x + a3.x) * inv)));
            o4.y = 1.0f / (1.0f + __expf(-(bi.y + (a0.y + a1.y + a2.y + a3.y) * inv)));
            o4.z = 1.0f / (1.0f + __expf(-(bi.z + (a0.z + a1.z + a2.z + a3.z) * inv)));
            o4.w = 1.0f / (1.0f + __expf(-(bi.w + (a0.w + a1.w + a2.w + a3.w) * inv)));
            reinterpret_cast<float4*>(out)[s] = o4;
            g_done[s] = 0;   // reset for next invocation (graph replay safe)
        }
    }
}

extern "C" void kernel_launch(void* const* d_in, const int* in_sizes, int n_in,
                              void* d_out, int out_size) {
    const float* x        = (const float*)d_in[0];
    const int*   node_num = (const int*)  d_in[1];
    const float* W        = (const float*)d_in[2];
    const float* bias     = (const float*)d_in[3];
    float*       out      = (float*)d_out;

    const int B = in_sizes[1];   // 4096 segments

    segmean_kernel<<<4 * B, 256>>>(x, node_num, W, bias, out, B);
}

// round 17
// speedup vs baseline: 1.3692x; 1.0798x over previous
#include <cuda_runtime.h>
#include <cuda_bf16.h>

// Precomputed exclusive prefix offsets of node_num
__device__ int g_off[8193];
// Cross-part combine state (zero-initialized at module load; each use resets)
__device__ float4 g_part4[8192 * 4];   // per (segment, quarter) partial dots
__device__ int    g_done[8192];        // arrival counters, reset by last arriver

// ---------------------------------------------------------------------------
// Kernel 1: single-block exclusive scan, 256 threads, warp-shuffle based.
// (proven in R9)
// ---------------------------------------------------------------------------
__global__ __launch_bounds__(256)
void scan_kernel(const int* __restrict__ node_num, int B) {
    const int tid  = threadIdx.x;
    const int lane = tid & 31;
    const int warp = tid >> 5;
    const int items = (B + 255) >> 8;          // 16 for B=4096

    int v[32];
    const int base = tid * items;
    int tsum = 0;
    for (int i = 0; i < items && i < 32; ++i) {
        int idx = base + i;
        int val = (idx < B) ? node_num[idx] : 0;
        v[i] = tsum;
        tsum += val;
    }

    int inc = tsum;
    #pragma unroll
    for (int off = 1; off < 32; off <<= 1) {
        int n = __shfl_up_sync(0xFFFFFFFFu, inc, off);
        if (lane >= off) inc += n;
    }

    __shared__ int wtot[8];
    if (lane == 31) wtot[warp] = inc;
    __syncthreads();

    int wbase = 0;
    #pragma unroll
    for (int w = 0; w < 8; ++w)
        if (w < warp) wbase += wtot[w];

    const int excl = wbase + inc - tsum;

    for (int i = 0; i < items && i < 32; ++i) {
        int idx = base + i;
        if (idx < B) g_off[idx] = excl + v[i];
    }
    if (tid == 255) g_off[B] = wbase + inc;
}

// ---------------------------------------------------------------------------
// Kernel 2: quarter-segment granularity, O(1) prologue (g_off lookup).
// Grid = 4*B. CTA c handles quarter q = c&3 of segment s = c>>2.
// Mainloop: proven .cs float4 stream; thread t owns columns 4*(t&63)..+3.
// Epilogue: block-reduce dot partials -> float4 slot; 4th arriver combines
// in fixed order, sigmoid, writes out, resets counter (graph-replay safe).
// ---------------------------------------------------------------------------
__global__ __launch_bounds__(256, 8)
void segmean_kernel(const float* __restrict__ x,
                    const int*   __restrict__ node_num,
                    const float* __restrict__ W,     // [4,256]
                    const float* __restrict__ bias,  // [4]
                    float*       __restrict__ out,   // [B,4]
                    int B)
{
    const int c    = blockIdx.x;
    const int s    = c >> 2;
    const int q    = c & 3;
    const int t    = threadIdx.x;
    const int warp = t >> 5;
    const int lane = t & 31;

    const int start = g_off[s];
    const int cnt   = __ldg(&node_num[s]);

    // this quarter's row range
    const int r0 = (q * cnt) >> 2;
    const int r1 = ((q + 1) * cnt) >> 2;
    const int n  = r1 - r0;

    // ---- streaming column sums over n rows ----
    const float4* p = reinterpret_cast<const float4*>(x + (size_t)(start + r0) * 256) + t;

    float4 sA = make_float4(0.f, 0.f, 0.f, 0.f);
    float4 sB = make_float4(0.f, 0.f, 0.f, 0.f);

    const int nIter = n >> 2;               // 4-row groups
    int i = 0;
    for (; i + 2 <= nIter; i += 2) {
        float4 a = __ldcs(p);
        float4 d = __ldcs(p + 256);
        sA.x += a.x; sA.y += a.y; sA.z += a.z; sA.w += a.w;
        sB.x += d.x; sB.y += d.y; sB.z += d.z; sB.w += d.w;
        p += 512;
    }
    if (nIter & 1) {
        float4 a = __ldcs(p);
        sA.x += a.x; sA.y += a.y; sA.z += a.z; sA.w += a.w;
        p += 256;
    }
    const int tailN = (n & 3) << 6;         // tail rows as flat float4s
    if (t < tailN) {
        float4 a = __ldcs(p);
        sB.x += a.x; sB.y += a.y; sB.z += a.z; sB.w += a.w;
    }

    float4 sv;
    sv.x = sA.x + sB.x;
    sv.y = sA.y + sB.y;
    sv.z = sA.z + sB.z;
    sv.w = sA.w + sB.w;

    // ---- partial dots with W over this thread's 4 columns ----
    const int c4 = (t & 63) << 2;
    const float4 w0 = *reinterpret_cast<const float4*>(W + c4);
    const float4 w1 = *reinterpret_cast<const float4*>(W + 256 + c4);
    const float4 w2 = *reinterpret_cast<const float4*>(W + 512 + c4);
    const float4 w3 = *reinterpret_cast<const float4*>(W + 768 + c4);

    float p0 = sv.x * w0.x + sv.y * w0.y + sv.z * w0.z + sv.w * w0.w;
    float p1 = sv.x * w1.x + sv.y * w1.y + sv.z * w1.z + sv.w * w1.w;
    float p2 = sv.x * w2.x + sv.y * w2.y + sv.z * w2.z + sv.w * w2.w;
    float p3 = sv.x * w3.x + sv.y * w3.y + sv.z * w3.z + sv.w * w3.w;

    #pragma unroll
    for (int off = 16; off > 0; off >>= 1) {
        p0 += __shfl_down_sync(0xFFFFFFFFu, p0, off);
        p1 += __shfl_down_sync(0xFFFFFFFFu, p1, off);
        p2 += __shfl_down_sync(0xFFFFFFFFu, p2, off);
        p3 += __shfl_down_sync(0xFFFFFFFFu, p3, off);
    }

    __shared__ float part[8][4];
    if (lane == 0) {
        part[warp][0] = p0;
        part[warp][1] = p1;
        part[warp][2] = p2;
        part[warp][3] = p3;
    }
    __syncthreads();

    // ---- single-thread combine/publish ----
    if (t == 0) {
        float4 mine;
        mine.x = part[0][0] + part[1][0] + part[2][0] + part[3][0]
               + part[4][0] + part[5][0] + part[6][0] + part[7][0];
        mine.y = part[0][1] + part[1][1] + part[2][1] + part[3][1]
               + part[4][1] + part[5][1] + part[6][1] + part[7][1];
        mine.z = part[0][2] + part[1][2] + part[2][2] + part[3][2]
               + part[4][2] + part[5][2] + part[6][2] + part[7][2];
        mine.w = part[0][3] + part[1][3] + part[2][3] + part[3][3]
               + part[4][3] + part[5][3] + part[6][3] + part[7][3];

        g_part4[(s << 2) + q] = mine;
        __threadfence();
        int old = atomicAdd(&g_done[s], 1);
        if (old == 3) {
            // last arriver: deterministic fixed-order combine
            float4 a0 = g_part4[(s << 2) + 0];
            float4 a1 = g_part4[(s << 2) + 1];
            float4 a2 = g_part4[(s << 2) + 2];
            float4 a3 = g_part4[(s << 2) + 3];
            const float inv = 1.0f / (float)cnt;
            const float4 bi = *reinterpret_cast<const float4*>(bias);
            float4 o4;
            o4.x = 1.0f / (1.0f + __expf(-(bi.x + (a0.x + a1.x + a2.x + a3.x) * inv)));
            o4.y = 1.0f / (1.0f + __expf(-(bi.y + (a0.y + a1.y + a2.y + a3.y) * inv)));
            o4.z = 1.0f / (1.0f + __expf(-(bi.z + (a0.z + a1.z + a2.z + a3.z) * inv)));
            o4.w = 1.0f / (1.0f + __expf(-(bi.w + (a0.w + a1.w + a2.w + a3.w) * inv)));
            reinterpret_cast<float4*>(out)[s] = o4;
            g_done[s] = 0;   // reset for next invocation (graph replay safe)
        }
    }
}

extern "C" void kernel_launch(void* const* d_in, const int* in_sizes, int n_in,
                              void* d_out, int out_size) {
    const float* x        = (const float*)d_in[0];
    const int*   node_num = (const int*)  d_in[1];
    const float* W        = (const float*)d_in[2];
    const float* bias     = (const float*)d_in[3];
    float*       out      = (float*)d_out;

    const int B = in_sizes[1];   // 4096 segments

    scan_kernel<<<1, 256>>>(node_num, B);
    segmean_kernel<<<4 * B, 256>>>(x, node_num, W, bias, out, B);
}